// round 4
// baseline (speedup 1.0000x reference)
#include <cuda_runtime.h>

// Chunked SSM:  T=64 chunk, M=64 chunks, n=64 state, CH=128 channels, B=16.
// y[b,c,m*64+jj] = Toeplitz(k, u_chunk) + Ghat[jj]·x[b,m] + D[c]*u
// Ghat[jj] = C·A^(jj+1) built as CH[hi]·AP[l], jj+1 = 8*hi + l.
// Single GEMM per channel: Y(64x1024) = [Ktoep | Ghat](64x128) @ [U ; X](128x1024)

#define APAD 68
#define ZPAD 132

__device__ float g_AP[9][4096];      // A_bar^p, p=1..8
__device__ float g_A16[4096], g_A32[4096], g_A64[4096];
__device__ float g_CH[8][8192];      // CH[h] = C * A8^h  (h=1..7; h=0 -> use C)
__device__ float g_W[64][64];        // W[j] = A_bar^j B_bar
__device__ float g_ktab[64][128];    // k[j][c]
__device__ float g_G[64][8192];      // Ghat[jj][c*64+s] = (C A^{jj+1})[c][s]
__device__ float g_Z[128][1024];     // rows 0..63 u-chunks, 64..127 states

// ---------------- packed f32x2 helpers (FFMA2) ----------------
#define PACK2(d, x) asm("mov.b64 %0, {%1, %1};" : "=l"(d) : "r"(__float_as_uint(x)))
#define FMA2(d, a, b) asm("fma.rn.f32x2 %0, %1, %2, %0;" : "+l"(d) : "l"(a), "l"(b))

__device__ __forceinline__ float f32x2_get(unsigned long long v, int hi) {
    return hi ? __uint_as_float((unsigned)(v >> 32)) : __uint_as_float((unsigned)v);
}

// ---------------- small matmul helpers (all smem) ----------------
__device__ __forceinline__ void load64(const float* __restrict__ G, float* s, int tid) {
    for (int idx = tid; idx < 4096; idx += 256)
        s[(idx >> 6) * 65 + (idx & 63)] = G[idx];
}
__device__ __forceinline__ void mm64_compute(const float* xs, const float* ys,
                                             float* __restrict__ O, int tid) {
    for (int idx = tid; idx < 4096; idx += 256) {
        int i = idx >> 6, t = idx & 63;
        float a0 = 0, a1 = 0, a2 = 0, a3 = 0;
        #pragma unroll
        for (int s = 0; s < 64; s += 4) {
            a0 += xs[i * 65 + s]     * ys[s * 65 + t];
            a1 += xs[i * 65 + s + 1] * ys[(s + 1) * 65 + t];
            a2 += xs[i * 65 + s + 2] * ys[(s + 2) * 65 + t];
            a3 += xs[i * 65 + s + 3] * ys[(s + 3) * 65 + t];
        }
        O[idx] = (a0 + a1) + (a2 + a3);
    }
}

// ---------------------------------------------------------------------------
// K1: discretization via column-parallel forward substitution (E lower-tri),
// then w-chain (W[0..7]) and A^2, all in one block.
// ---------------------------------------------------------------------------
__global__ __launch_bounds__(1024) void k_disc(const float* __restrict__ A,
                                               const float* __restrict__ B,
                                               const float* __restrict__ dtp) {
    __shared__ float As_[64 * 65];
    __shared__ float Xs[64 * 66];
    __shared__ float Bs[64], rdiag[64];
    __shared__ float wv[2][64];
    int tid = threadIdx.x;
    float dt = dtp[0], hd = 0.5f * dt;
    for (int idx = tid; idx < 4096; idx += 1024)
        As_[(idx >> 6) * 65 + (idx & 63)] = A[idx];
    if (tid < 64) Bs[tid] = B[tid];
    __syncthreads();
    if (tid < 64) rdiag[tid] = 1.f / (1.f - hd * As_[tid * 65 + tid]);
    __syncthreads();
    // Solve E X = [F | dt*B],  E = I - hd*A (lower-tri), F = I + hd*A.
    if (tid < 65) {
        int c = tid;
        for (int i = 0; i < 64; i++) {
            float acc0, acc1 = 0.f;
            if (c < 64) acc0 = ((i == c) ? 1.f : 0.f) + hd * As_[i * 65 + c];
            else        acc0 = dt * Bs[i];
            int j = 0;
            for (; j + 1 < i; j += 2) {
                acc0 += hd * As_[i * 65 + j]     * Xs[j * 66 + c];
                acc1 += hd * As_[i * 65 + j + 1] * Xs[(j + 1) * 66 + c];
            }
            if (j < i) acc0 += hd * As_[i * 65 + j] * Xs[j * 66 + c];
            Xs[i * 66 + c] = (acc0 + acc1) * rdiag[i];
        }
    }
    __syncthreads();
    // store A_bar, B_bar (=W[0])
    for (int idx = tid; idx < 4096; idx += 1024)
        g_AP[1][idx] = Xs[(idx >> 6) * 66 + (idx & 63)];
    if (tid < 64) { g_W[0][tid] = Xs[tid * 66 + 64]; wv[0][tid] = Xs[tid * 66 + 64]; }
    __syncthreads();
    // w chain: W[r] = A_bar^r B_bar, r=1..7
    int cur = 0;
    for (int r = 1; r < 8; r++) {
        if (tid < 64) {
            float acc = 0.f;
            #pragma unroll 8
            for (int s = 0; s < 64; s++) acc += Xs[tid * 66 + s] * wv[cur][s];
            wv[1 - cur][tid] = acc;
            g_W[r][tid] = acc;
        }
        __syncthreads();
        cur ^= 1;
    }
    // A2 = A_bar^2
    for (int idx = tid; idx < 4096; idx += 1024) {
        int i = idx >> 6, t = idx & 63;
        float a0 = 0, a1 = 0, a2 = 0, a3 = 0;
        #pragma unroll
        for (int s = 0; s < 64; s += 4) {
            a0 += Xs[i * 66 + s]     * Xs[s * 66 + t];
            a1 += Xs[i * 66 + s + 1] * Xs[(s + 1) * 66 + t];
            a2 += Xs[i * 66 + s + 2] * Xs[(s + 2) * 66 + t];
            a3 += Xs[i * 66 + s + 3] * Xs[(s + 3) * 66 + t];
        }
        g_AP[2][idx] = (a0 + a1) + (a2 + a3);
    }
}

// ---------------------------------------------------------------------------
// K2..K6: power/CH stages. All products are 64-row blocks through smem.
//  stage 0 (2 blk): A3=A2*A1, A4=A2*A2
//  stage 1 (4 blk): A5..A8 = A4*A{1..4}
//  stage 2 (4 blk): A16=A8^2 | CH1=C*A8 (2 blk) | W chain (W[8..63] via A8)
//  stage 3 (5 blk): A32=A16^2 | CH2=C*A16 | CH3=CH1*A16
//  stage 4 (9 blk): A64=A32^2 | CH4..7 = {C,CH1,CH2,CH3}*A32
// ---------------------------------------------------------------------------
__global__ __launch_bounds__(256) void k_stage(int stage, const float* __restrict__ C) {
    __shared__ float sm1[64 * 65], sm2[64 * 65];
    __shared__ float Wb[2][512];
    int tid = threadIdx.x, bid = blockIdx.x;
    const float* Xp; const float* Yp; float* Op;
    if (stage == 0) {
        Xp = g_AP[2]; Yp = (bid == 0) ? g_AP[1] : g_AP[2]; Op = (bid == 0) ? g_AP[3] : g_AP[4];
    } else if (stage == 1) {
        Xp = g_AP[4]; Yp = g_AP[1 + bid]; Op = g_AP[5 + bid];
    } else if (stage == 2) {
        if (bid == 0)      { Xp = g_AP[8]; Yp = g_AP[8]; Op = g_A16; }
        else if (bid <= 2) { Xp = C + (bid - 1) * 4096; Yp = g_AP[8]; Op = g_CH[1] + (bid - 1) * 4096; }
        else {
            // W chain: W[8q+r] = A8 * W[8(q-1)+r]
            load64(g_AP[8], sm1, tid);
            for (int idx = tid; idx < 512; idx += 256) Wb[0][idx] = g_W[idx >> 6][idx & 63];
            __syncthreads();
            int cur = 0;
            for (int q = 1; q < 8; q++) {
                float res[2];
                #pragma unroll
                for (int h = 0; h < 2; h++) {
                    int idx = tid + h * 256;
                    int r = idx >> 6, i = idx & 63;
                    float a0 = 0, a1 = 0;
                    #pragma unroll 8
                    for (int s = 0; s < 64; s += 2) {
                        a0 += sm1[i * 65 + s]     * Wb[cur][r * 64 + s];
                        a1 += sm1[i * 65 + s + 1] * Wb[cur][r * 64 + s + 1];
                    }
                    res[h] = a0 + a1;
                }
                __syncthreads();
                #pragma unroll
                for (int h = 0; h < 2; h++) {
                    int idx = tid + h * 256;
                    int r = idx >> 6, i = idx & 63;
                    Wb[1 - cur][r * 64 + i] = res[h];
                    g_W[8 * q + r][i] = res[h];
                }
                __syncthreads();
                cur ^= 1;
            }
            return;
        }
    } else if (stage == 3) {
        if (bid == 0)      { Xp = g_A16; Yp = g_A16; Op = g_A32; }
        else if (bid <= 2) { Xp = C + (bid - 1) * 4096;        Yp = g_A16; Op = g_CH[2] + (bid - 1) * 4096; }
        else               { Xp = g_CH[1] + (bid - 3) * 4096;  Yp = g_A16; Op = g_CH[3] + (bid - 3) * 4096; }
    } else {
        if (bid == 0) { Xp = g_A32; Yp = g_A32; Op = g_A64; }
        else {
            int p = bid - 1, which = p >> 1, half = p & 1;
            const float* srcs[4] = { C, g_CH[1], g_CH[2], g_CH[3] };
            Xp = srcs[which] + half * 4096;
            Yp = g_A32;
            Op = g_CH[4 + which] + half * 4096;
        }
    }
    load64(Xp, sm1, tid);
    load64(Yp, sm2, tid);
    __syncthreads();
    mm64_compute(sm1, sm2, Op, tid);
}

// ---------------------------------------------------------------------------
// K7: Ghat[jj] = CH[hi] * AP[l]  (blocks 0..127, 2 per jj) ; ktab (blocks 128/129)
// ---------------------------------------------------------------------------
__global__ __launch_bounds__(256) void k_ghat(const float* __restrict__ C) {
    __shared__ float sm1[64 * 65], sm2[64 * 65];
    __shared__ float ws[512];
    int tid = threadIdx.x, bid = blockIdx.x;
    if (bid < 128) {
        int jj = bid >> 1, ch0 = (bid & 1) * 64;
        int hi = jj >> 3, l = (jj & 7) + 1;
        const float* CHp = (hi == 0) ? C : g_CH[hi];
        for (int idx = tid; idx < 4096; idx += 256)
            sm1[(idx >> 6) * 65 + (idx & 63)] = CHp[ch0 * 64 + idx];
        load64(g_AP[l], sm2, tid);
        __syncthreads();
        mm64_compute(sm1, sm2, g_G[jj] + ch0 * 64, tid);
    } else {
        for (int idx = tid; idx < 512; idx += 256) ws[idx] = g_W[idx >> 6][idx & 63];
        __syncthreads();
        int j0 = (bid - 128) * 32;
        for (int idx = tid; idx < 4096; idx += 256) {
            int j = j0 + (idx >> 7), c = idx & 127;
            int hi = j >> 3, lo = j & 7;
            const float* CHr = ((hi == 0) ? C : g_CH[hi]) + c * 64;
            float a0 = 0, a1 = 0;
            #pragma unroll 8
            for (int s = 0; s < 64; s += 2) {
                a0 += CHr[s]     * ws[lo * 64 + s];
                a1 += CHr[s + 1] * ws[lo * 64 + s + 1];
            }
            g_ktab[j][c] = a0 + a1;
        }
    }
}

// ---------------------------------------------------------------------------
// K8: per-batch chunk projection S = F @ u_chunks, state scan, write Z.
// ---------------------------------------------------------------------------
__global__ __launch_bounds__(256) void k_prep(const float* __restrict__ u) {
    extern __shared__ float sm[];
    float* us  = sm;                  // [64][66]
    float* Fs  = sm + 64 * 66;        // [64][65]  Fs[i][s] = W[63-i][s]
    float* Sm  = Fs + 64 * 65;        // [64][65]
    float* ATs = Sm + 64 * 65;        // [64][65]  A_bar^64
    float* xv  = ATs + 64 * 65;       // [64]
    float* part = xv + 64;            // [4][64]
    int tid = threadIdx.x, b = blockIdx.x;
    for (int idx = tid; idx < 4096; idx += 256) {
        int m = idx >> 6, j = idx & 63;
        us[m * 66 + j] = u[b * 4096 + idx];
    }
    for (int idx = tid; idx < 4096; idx += 256) {
        int i = idx >> 6, s = idx & 63;
        Fs[i * 65 + s]  = g_W[63 - i][s];
        ATs[i * 65 + s] = g_A64[idx];
    }
    __syncthreads();
    for (int idx = tid; idx < 4096; idx += 256) {
        int m = idx >> 6, s = idx & 63;
        float acc = 0.f;
        #pragma unroll 8
        for (int i = 0; i < 64; i++) acc += Fs[i * 65 + s] * us[m * 66 + i];
        Sm[m * 65 + s] = acc;
    }
    for (int idx = tid; idx < 4096; idx += 256) {
        int j = idx >> 6, m = idx & 63;
        g_Z[j][b * 64 + m] = us[m * 66 + j];
    }
    if (tid < 64) xv[tid] = 0.f;
    __syncthreads();
    int s = tid & 63, q = tid >> 6;
    for (int m = 0; m < 64; m++) {
        if (q == 0) g_Z[64 + s][b * 64 + m] = xv[s];
        float acc = 0.f;
        #pragma unroll
        for (int s2 = q * 16; s2 < q * 16 + 16; s2++) acc += ATs[s * 65 + s2] * xv[s2];
        part[q * 64 + s] = acc;
        __syncthreads();
        if (q == 0)
            xv[s] = part[s] + part[64 + s] + part[128 + s] + part[192 + s] + Sm[m * 65 + s];
        __syncthreads();
    }
}

// ---------------------------------------------------------------------------
// K9: GEMM. Block = (channel c, 128 cols). A-tile 128x64 (Toeplitz | Ghat^T),
// Z-tile 128x128. 16x16 threads, 4x8 micro-tile via packed fma.rn.f32x2.
// ---------------------------------------------------------------------------
__global__ __launch_bounds__(256) void k_gemm(const float* __restrict__ D,
                                              float* __restrict__ out) {
    extern __shared__ float sm[];
    float* As = sm;                   // [128][APAD]  As[k][jj]
    float* Zs = sm + 128 * APAD;      // [128][ZPAD]
    float* kt = Zs + 128 * ZPAD;      // [64]
    int tid = threadIdx.x;
    int n0 = blockIdx.x * 128;
    int c  = blockIdx.y;

    for (int idx = tid; idx < 64; idx += 256) kt[idx] = g_ktab[idx][c];
    for (int idx = tid; idx < 4096; idx += 256) {
        int jj = idx >> 6, s = idx & 63;
        As[(64 + s) * APAD + jj] = g_G[jj][c * 64 + s];
    }
    for (int idx = tid; idx < 16384; idx += 256) {
        int k = idx >> 7, n = idx & 127;
        Zs[k * ZPAD + n] = g_Z[k][n0 + n];
    }
    __syncthreads();
    for (int idx = tid; idx < 4096; idx += 256) {
        int k = idx >> 6, jj = idx & 63;
        As[k * APAD + jj] = (k <= jj) ? kt[jj - k] : 0.f;
    }
    __syncthreads();

    int tr = tid & 15, tc = tid >> 4;
    unsigned long long acc[4][4];
    #pragma unroll
    for (int i = 0; i < 4; i++)
        #pragma unroll
        for (int j = 0; j < 4; j++) acc[i][j] = 0ull;

    #pragma unroll 2
    for (int k = 0; k < 128; k++) {
        float4 av = *(const float4*)&As[k * APAD + tr * 4];
        ulonglong2 zl = *(const ulonglong2*)&Zs[k * ZPAD + tc * 4];
        ulonglong2 zh = *(const ulonglong2*)&Zs[k * ZPAD + 64 + tc * 4];
        unsigned long long ap[4], zp[4];
        zp[0] = zl.x; zp[1] = zl.y; zp[2] = zh.x; zp[3] = zh.y;
        PACK2(ap[0], av.x); PACK2(ap[1], av.y); PACK2(ap[2], av.z); PACK2(ap[3], av.w);
        #pragma unroll
        for (int ri = 0; ri < 4; ri++)
            #pragma unroll
            for (int cj = 0; cj < 4; cj++)
                FMA2(acc[ri][cj], ap[ri], zp[cj]);
    }

    float Dv = D[c];
    #pragma unroll
    for (int q = 0; q < 8; q++) {
        int n  = (q < 4) ? (tc * 4 + q) : (64 + tc * 4 + (q - 4));
        int cj = q >> 1;
        int lh = q & 1;
        int gn = n0 + n, b = gn >> 6, mm = gn & 63;
        float4 o;
        o.x = f32x2_get(acc[0][cj], lh) + Dv * Zs[(tr * 4 + 0) * ZPAD + n];
        o.y = f32x2_get(acc[1][cj], lh) + Dv * Zs[(tr * 4 + 1) * ZPAD + n];
        o.z = f32x2_get(acc[2][cj], lh) + Dv * Zs[(tr * 4 + 2) * ZPAD + n];
        o.w = f32x2_get(acc[3][cj], lh) + Dv * Zs[(tr * 4 + 3) * ZPAD + n];
        *(float4*)&out[(b * 128 + c) * 4096 + mm * 64 + tr * 4] = o;
    }
}

// ---------------------------------------------------------------------------
extern "C" void kernel_launch(void* const* d_in, const int* in_sizes, int n_in,
                              void* d_out, int out_size) {
    const float *u = 0, *A = 0, *B = 0, *C = 0, *D = 0, *dt = 0;
    for (int i = 0; i < n_in; i++) {
        const float* p = (const float*)d_in[i];
        switch (in_sizes[i]) {
            case 65536: u = p;  break;
            case 4096:  A = p;  break;
            case 64:    B = p;  break;
            case 8192:  C = p;  break;
            case 128:   D = p;  break;
            case 1:     dt = p; break;
        }
    }
    const int prep_smem = (64 * 66 + 3 * 64 * 65 + 64 + 256) * sizeof(float);       // 68096
    const int gemm_smem = (128 * APAD + 128 * ZPAD + 64) * sizeof(float);           // 102656
    cudaFuncSetAttribute(k_prep, cudaFuncAttributeMaxDynamicSharedMemorySize, prep_smem);
    cudaFuncSetAttribute(k_gemm, cudaFuncAttributeMaxDynamicSharedMemorySize, gemm_smem);

    k_disc<<<1, 1024>>>(A, B, dt);
    k_stage<<<2, 256>>>(0, C);
    k_stage<<<4, 256>>>(1, C);
    k_stage<<<4, 256>>>(2, C);
    k_stage<<<5, 256>>>(3, C);
    k_stage<<<9, 256>>>(4, C);
    k_ghat<<<130, 256>>>(C);
    k_prep<<<16, 256, prep_smem>>>(u);
    k_gemm<<<dim3(8, 128), 256, gemm_smem>>>(D, (float*)d_out);
}

// round 5
// speedup vs baseline: 3.0342x; 3.0342x over previous
#include <cuda_runtime.h>

// Chunked SSM:  T=64 chunk, M=64 chunks, n=64 state, CH=128 channels, B=16.
// y[b,c,m*64+jj] = Toeplitz(k, u_chunk) + Ghat[jj]·x[b,m] + D[c]*u
// Ghat[jj] = CH[hi]·A^l, jj+1 = 8*hi + l;  CH[h] = C·A8^h via per-row chains.
// GEMM per channel: Y(64x1024) = [Ktoep | Ghat](64x128) @ [U ; X](128x1024)

#define APAD 68
#define ZPAD 132
#define MPAD 68

__device__ float g_AP[9][4096];      // A_bar^p, p=1..8
__device__ float g_A64[4096];        // A_bar^64 (for the state scan)
__device__ float g_CH[8][8192];      // CH[h] = C * A8^h (h=1..7)
__device__ float g_W[64][64];        // W[j] = A_bar^j B_bar
__device__ float g_ktab[64][128];    // k[j][c]
__device__ float g_G[64][8192];      // Ghat[jj][c*64+s]
__device__ float g_Z[128][1024];     // rows 0..63 u-chunks, 64..127 states

// ---------------- packed f32x2 helpers ----------------
#define PACK2(d, x) asm("mov.b64 %0, {%1, %1};" : "=l"(d) : "r"(__float_as_uint(x)))
#define FMA2(d, a, b) asm("fma.rn.f32x2 %0, %1, %2, %0;" : "+l"(d) : "l"(a), "l"(b))

__device__ __forceinline__ float f32x2_get(unsigned long long v, int hi) {
    return hi ? __uint_as_float((unsigned)(v >> 32)) : __uint_as_float((unsigned)v);
}

// ---------------- register-blocked 64x64 matmul core ----------------
// O[i][t] = sum_s xT[s][i] * ys[s][t].  xT/ys pitch MPAD (16B aligned rows).
// 256 threads, thread computes 4x4 tile. 2x LDS.128 + 16 FFMA per k-step.
__device__ __forceinline__ void mm64R(const float* __restrict__ xT,
                                      const float* __restrict__ ys,
                                      float* __restrict__ O, int tid) {
    int tr = tid & 15, tc = tid >> 4;
    float a00=0,a01=0,a02=0,a03=0, a10=0,a11=0,a12=0,a13=0;
    float a20=0,a21=0,a22=0,a23=0, a30=0,a31=0,a32=0,a33=0;
    #pragma unroll 4
    for (int s = 0; s < 64; s++) {
        float4 xv = *(const float4*)(xT + s * MPAD + tr * 4);
        float4 yv = *(const float4*)(ys + s * MPAD + tc * 4);
        a00 += xv.x*yv.x; a01 += xv.x*yv.y; a02 += xv.x*yv.z; a03 += xv.x*yv.w;
        a10 += xv.y*yv.x; a11 += xv.y*yv.y; a12 += xv.y*yv.z; a13 += xv.y*yv.w;
        a20 += xv.z*yv.x; a21 += xv.z*yv.y; a22 += xv.z*yv.z; a23 += xv.z*yv.w;
        a30 += xv.w*yv.x; a31 += xv.w*yv.y; a32 += xv.w*yv.z; a33 += xv.w*yv.w;
    }
    float4 o0 = {a00,a01,a02,a03}; *(float4*)(O + (tr*4+0)*64 + tc*4) = o0;
    float4 o1 = {a10,a11,a12,a13}; *(float4*)(O + (tr*4+1)*64 + tc*4) = o1;
    float4 o2 = {a20,a21,a22,a23}; *(float4*)(O + (tr*4+2)*64 + tc*4) = o2;
    float4 o3 = {a30,a31,a32,a33}; *(float4*)(O + (tr*4+3)*64 + tc*4) = o3;
}

__device__ __forceinline__ void loadT(const float* __restrict__ G, float* xT, int tid) {
    for (int idx = tid; idx < 4096; idx += 256) {
        int i = idx >> 6, s = idx & 63;
        xT[s * MPAD + i] = G[idx];
    }
}
__device__ __forceinline__ void loadN(const float* __restrict__ G, float* ys, int tid) {
    for (int idx = tid; idx < 4096; idx += 256)
        ys[(idx >> 6) * MPAD + (idx & 63)] = G[idx];
}

// ---------------------------------------------------------------------------
// K1: discretization. E = I - hd*A lower-tri. Column-parallel forward
// substitution (each thread owns one column -> no syncs in the solve).
// Then W[0..7] chain and A2 = A_bar^2 (register-blocked).
// ---------------------------------------------------------------------------
__global__ __launch_bounds__(256) void k_disc(const float* __restrict__ A,
                                              const float* __restrict__ B,
                                              const float* __restrict__ dtp) {
    extern __shared__ float sm[];
    float* Ao = sm;                 // [64][65]
    float* Xs = sm + 64 * 65;       // [64][MPAD]  cols 0..63 A_bar, col 64 B_bar
    float* xT = Xs + 64 * MPAD;     // [64][MPAD]  A_bar transposed
    __shared__ float rdiag[64];
    __shared__ float wv[2][64];
    int tid = threadIdx.x;
    float dt = dtp[0], hd = 0.5f * dt;
    for (int idx = tid; idx < 4096; idx += 256)
        Ao[(idx >> 6) * 65 + (idx & 63)] = A[idx];
    __syncthreads();
    if (tid < 64) rdiag[tid] = 1.f / (1.f - hd * Ao[tid * 65 + tid]);
    __syncthreads();
    if (tid < 65) {
        int c = tid;
        for (int i = 0; i < 64; i++) {
            float acc0, acc1 = 0.f;
            if (c < 64) acc0 = ((i == c) ? 1.f : 0.f) + hd * Ao[i * 65 + c];
            else        acc0 = dt * B[i];
            int j = 0;
            for (; j + 1 < i; j += 2) {
                acc0 += hd * Ao[i * 65 + j]     * Xs[j * MPAD + c];
                acc1 += hd * Ao[i * 65 + j + 1] * Xs[(j + 1) * MPAD + c];
            }
            if (j < i) acc0 += hd * Ao[i * 65 + j] * Xs[j * MPAD + c];
            Xs[i * MPAD + c] = (acc0 + acc1) * rdiag[i];
        }
    }
    __syncthreads();
    for (int idx = tid; idx < 4096; idx += 256) {
        int i = idx >> 6, s = idx & 63;
        float v = Xs[i * MPAD + s];
        g_AP[1][idx] = v;
        xT[s * MPAD + i] = v;
    }
    if (tid < 64) { float b0 = Xs[tid * MPAD + 64]; g_W[0][tid] = b0; wv[0][tid] = b0; }
    __syncthreads();
    int cur = 0;
    for (int r = 1; r < 8; r++) {
        if (tid < 64) {
            float a0 = 0, a1 = 0;
            #pragma unroll 8
            for (int s = 0; s < 64; s += 2) {
                a0 += Xs[tid * MPAD + s]     * wv[cur][s];
                a1 += Xs[tid * MPAD + s + 1] * wv[cur][s + 1];
            }
            wv[1 - cur][tid] = a0 + a1; g_W[r][tid] = a0 + a1;
        }
        __syncthreads();
        cur ^= 1;
    }
    mm64R(xT, Xs, g_AP[2], tid);
}

// ---------------------------------------------------------------------------
// K2/K3: power products.
//  stage 0 (2 blk): A4=A2*A2, A3=A1*A2
//  stage 1 (4 blk): A8=A4*A4, A5=A4*A1, A6=A4*A2, A7=A4*A3
// ---------------------------------------------------------------------------
__global__ __launch_bounds__(256) void k_mul(int stage) {
    __shared__ float xT[64 * MPAD];
    __shared__ float ys[64 * MPAD];
    int tid = threadIdx.x, bid = blockIdx.x;
    const float *X, *Y; float* O;
    if (stage == 0) {
        X = bid ? g_AP[1] : g_AP[2]; Y = g_AP[2]; O = bid ? g_AP[3] : g_AP[4];
    } else {
        X = g_AP[4]; Y = bid ? g_AP[bid] : g_AP[4]; O = bid ? g_AP[4 + bid] : g_AP[8];
    }
    loadT(X, xT, tid);
    loadN(Y, ys, tid);
    __syncthreads();
    mm64R(xT, ys, O, tid);
}

// ---------------------------------------------------------------------------
// K4: everything that depends only on A8 (parallel row-chains).
//  blocks 0..31 : CH chain, 4 channels/block: CH[h][c] = CH[h-1][c] * A8
//  blocks 32..47: A64 rows, 4 rows/block:     r^{(k+1)} = r^{(k)} * A8
//  block  48    : W chain:  W[8q+r] = A8 * W[8(q-1)+r]
// ---------------------------------------------------------------------------
__global__ __launch_bounds__(256) void k_chain(const float* __restrict__ C) {
    __shared__ float A8s[64 * 65];
    __shared__ float buf[1024];
    int tid = threadIdx.x, bid = blockIdx.x;
    for (int idx = tid; idx < 4096; idx += 256)
        A8s[(idx >> 6) * 65 + (idx & 63)] = g_AP[8][idx];

    if (bid < 48) {
        int grp = tid >> 6, s = tid & 63;
        float* v = buf;                      // [4][64]
        if (bid < 32) {
            int c0 = bid * 4;
            v[grp * 64 + s] = C[(c0 + grp) * 64 + s];
        } else {
            int r0 = (bid - 32) * 4;
            v[grp * 64 + s] = g_AP[8][(r0 + grp) * 64 + s];
        }
        __syncthreads();
        #pragma unroll 1
        for (int h = 1; h < 8; h++) {
            float a0 = 0, a1 = 0, a2 = 0, a3 = 0;
            #pragma unroll
            for (int s2 = 0; s2 < 64; s2 += 4) {
                a0 += v[grp * 64 + s2]     * A8s[s2 * 65 + s];
                a1 += v[grp * 64 + s2 + 1] * A8s[(s2 + 1) * 65 + s];
                a2 += v[grp * 64 + s2 + 2] * A8s[(s2 + 2) * 65 + s];
                a3 += v[grp * 64 + s2 + 3] * A8s[(s2 + 3) * 65 + s];
            }
            float nv = (a0 + a1) + (a2 + a3);
            __syncthreads();
            v[grp * 64 + s] = nv;
            if (bid < 32) g_CH[h][(bid * 4 + grp) * 64 + s] = nv;
            else if (h == 7) g_A64[((bid - 32) * 4 + grp) * 64 + s] = nv;
            __syncthreads();
        }
    } else {
        for (int idx = tid; idx < 512; idx += 256) buf[idx] = g_W[idx >> 6][idx & 63];
        __syncthreads();
        int cur = 0;
        for (int q = 1; q < 8; q++) {
            float res[2];
            #pragma unroll
            for (int h = 0; h < 2; h++) {
                int p = tid + h * 256;
                int r = p >> 6, i = p & 63;
                float a0 = 0, a1 = 0;
                #pragma unroll 8
                for (int s = 0; s < 64; s += 2) {
                    a0 += A8s[i * 65 + s]     * buf[cur * 512 + r * 64 + s];
                    a1 += A8s[i * 65 + s + 1] * buf[cur * 512 + r * 64 + s + 1];
                }
                res[h] = a0 + a1;
            }
            __syncthreads();
            #pragma unroll
            for (int h = 0; h < 2; h++) {
                int p = tid + h * 256;
                int r = p >> 6, i = p & 63;
                buf[(1 - cur) * 512 + r * 64 + i] = res[h];
                g_W[8 * q + r][i] = res[h];
            }
            __syncthreads();
            cur ^= 1;
        }
    }
}

// ---------------------------------------------------------------------------
// K5: Ghat[jj] = CH[hi] * A^l (blocks 0..127, two 64-channel halves per jj);
//     ktab (blocks 128..135, one per hi): ktab[8hi+lo][c] = CH[hi][c]·W[lo]
// ---------------------------------------------------------------------------
__global__ __launch_bounds__(256) void k_ghat(const float* __restrict__ C) {
    __shared__ float smu[8832];
    int tid = threadIdx.x, bid = blockIdx.x;
    if (bid < 128) {
        float* xT = smu;                // [64][MPAD]
        float* ys = smu + 64 * MPAD;    // [64][MPAD]
        int jj = bid >> 1, ch0 = (bid & 1) << 6;
        int hi = jj >> 3, l = (jj & 7) + 1;
        const float* __restrict__ CHp = hi ? g_CH[hi] : C;
        for (int idx = tid; idx < 4096; idx += 256) {
            int i = idx >> 6, s = idx & 63;
            xT[s * MPAD + i] = CHp[(ch0 + i) * 64 + s];
        }
        loadN(g_AP[l], ys, tid);
        __syncthreads();
        mm64R(xT, ys, g_G[jj] + ch0 * 64, tid);
    } else {
        float* CHs = smu;               // [128][65]
        float* ws  = smu + 128 * 65;    // [8][64]
        int hi = bid - 128;
        const float* __restrict__ CHp = hi ? g_CH[hi] : C;
        for (int idx = tid; idx < 8192; idx += 256)
            CHs[(idx >> 6) * 65 + (idx & 63)] = CHp[idx];
        for (int idx = tid; idx < 512; idx += 256) ws[idx] = g_W[idx >> 6][idx & 63];
        __syncthreads();
        int c = tid >> 1, lo0 = (tid & 1) * 4;
        float a0 = 0, a1 = 0, a2 = 0, a3 = 0;
        #pragma unroll 4
        for (int s = 0; s < 64; s++) {
            float cv = CHs[c * 65 + s];
            a0 += cv * ws[(lo0 + 0) * 64 + s];
            a1 += cv * ws[(lo0 + 1) * 64 + s];
            a2 += cv * ws[(lo0 + 2) * 64 + s];
            a3 += cv * ws[(lo0 + 3) * 64 + s];
        }
        g_ktab[hi * 8 + lo0 + 0][c] = a0;
        g_ktab[hi * 8 + lo0 + 1][c] = a1;
        g_ktab[hi * 8 + lo0 + 2][c] = a2;
        g_ktab[hi * 8 + lo0 + 3][c] = a3;
    }
}

// ---------------------------------------------------------------------------
// K6: per-batch chunk projection S = F @ u_chunks, state scan, write Z.
// ---------------------------------------------------------------------------
__global__ __launch_bounds__(256) void k_prep(const float* __restrict__ u) {
    extern __shared__ float sm[];
    float* us  = sm;                  // [64][66]
    float* Fs  = sm + 64 * 66;        // [64][65]  Fs[i][s] = W[63-i][s]
    float* Sm  = Fs + 64 * 65;        // [64][65]
    float* ATs = Sm + 64 * 65;        // [64][65]  A_bar^64
    float* xv  = ATs + 64 * 65;       // [64]
    float* part = xv + 64;            // [4][64]
    int tid = threadIdx.x, b = blockIdx.x;
    for (int idx = tid; idx < 4096; idx += 256) {
        int m = idx >> 6, j = idx & 63;
        us[m * 66 + j] = u[b * 4096 + idx];
    }
    for (int idx = tid; idx < 4096; idx += 256) {
        int i = idx >> 6, s = idx & 63;
        Fs[i * 65 + s]  = g_W[63 - i][s];
        ATs[i * 65 + s] = g_A64[idx];
    }
    __syncthreads();
    for (int idx = tid; idx < 4096; idx += 256) {
        int m = idx >> 6, s = idx & 63;
        float a0 = 0, a1 = 0;
        #pragma unroll 8
        for (int i = 0; i < 64; i += 2) {
            a0 += Fs[i * 65 + s]       * us[m * 66 + i];
            a1 += Fs[(i + 1) * 65 + s] * us[m * 66 + i + 1];
        }
        Sm[m * 65 + s] = a0 + a1;
    }
    for (int idx = tid; idx < 4096; idx += 256) {
        int j = idx >> 6, m = idx & 63;
        g_Z[j][b * 64 + m] = us[m * 66 + j];
    }
    if (tid < 64) xv[tid] = 0.f;
    __syncthreads();
    int s = tid & 63, q = tid >> 6;
    for (int m = 0; m < 64; m++) {
        if (q == 0) g_Z[64 + s][b * 64 + m] = xv[s];
        float acc = 0.f;
        #pragma unroll
        for (int s2 = q * 16; s2 < q * 16 + 16; s2++) acc += ATs[s * 65 + s2] * xv[s2];
        part[q * 64 + s] = acc;
        __syncthreads();
        if (q == 0)
            xv[s] = part[s] + part[64 + s] + part[128 + s] + part[192 + s] + Sm[m * 65 + s];
        __syncthreads();
    }
}

// ---------------------------------------------------------------------------
// K7: GEMM. Block = (channel c, 128 cols). A-tile 128x64 (Toeplitz | Ghat^T),
// Z-tile 128x128. 16x16 threads, 4x8 micro-tile via packed fma.rn.f32x2.
// ---------------------------------------------------------------------------
__global__ __launch_bounds__(256) void k_gemm(const float* __restrict__ D,
                                              float* __restrict__ out) {
    extern __shared__ float sm[];
    float* As = sm;                   // [128][APAD]  As[k][jj]
    float* Zs = sm + 128 * APAD;      // [128][ZPAD]
    float* kt = Zs + 128 * ZPAD;      // [64]
    int tid = threadIdx.x;
    int n0 = blockIdx.x * 128;
    int c  = blockIdx.y;

    for (int idx = tid; idx < 64; idx += 256) kt[idx] = g_ktab[idx][c];
    for (int idx = tid; idx < 4096; idx += 256) {
        int jj = idx >> 6, s = idx & 63;
        As[(64 + s) * APAD + jj] = g_G[jj][c * 64 + s];
    }
    for (int idx = tid; idx < 16384; idx += 256) {
        int k = idx >> 7, n = idx & 127;
        Zs[k * ZPAD + n] = g_Z[k][n0 + n];
    }
    __syncthreads();
    for (int idx = tid; idx < 4096; idx += 256) {
        int k = idx >> 6, jj = idx & 63;
        As[k * APAD + jj] = (k <= jj) ? kt[jj - k] : 0.f;
    }
    __syncthreads();

    int tr = tid & 15, tc = tid >> 4;
    unsigned long long acc[4][4];
    #pragma unroll
    for (int i = 0; i < 4; i++)
        #pragma unroll
        for (int j = 0; j < 4; j++) acc[i][j] = 0ull;

    #pragma unroll 2
    for (int k = 0; k < 128; k++) {
        float4 av = *(const float4*)&As[k * APAD + tr * 4];
        ulonglong2 zl = *(const ulonglong2*)&Zs[k * ZPAD + tc * 4];
        ulonglong2 zh = *(const ulonglong2*)&Zs[k * ZPAD + 64 + tc * 4];
        unsigned long long ap[4], zp[4];
        zp[0] = zl.x; zp[1] = zl.y; zp[2] = zh.x; zp[3] = zh.y;
        PACK2(ap[0], av.x); PACK2(ap[1], av.y); PACK2(ap[2], av.z); PACK2(ap[3], av.w);
        #pragma unroll
        for (int ri = 0; ri < 4; ri++)
            #pragma unroll
            for (int cj = 0; cj < 4; cj++)
                FMA2(acc[ri][cj], ap[ri], zp[cj]);
    }

    float Dv = D[c];
    #pragma unroll
    for (int q = 0; q < 8; q++) {
        int n  = (q < 4) ? (tc * 4 + q) : (64 + tc * 4 + (q - 4));
        int cj = q >> 1;
        int lh = q & 1;
        int gn = n0 + n, b = gn >> 6, mm = gn & 63;
        float4 o;
        o.x = f32x2_get(acc[0][cj], lh) + Dv * Zs[(tr * 4 + 0) * ZPAD + n];
        o.y = f32x2_get(acc[1][cj], lh) + Dv * Zs[(tr * 4 + 1) * ZPAD + n];
        o.z = f32x2_get(acc[2][cj], lh) + Dv * Zs[(tr * 4 + 2) * ZPAD + n];
        o.w = f32x2_get(acc[3][cj], lh) + Dv * Zs[(tr * 4 + 3) * ZPAD + n];
        *(float4*)&out[(b * 128 + c) * 4096 + mm * 64 + tr * 4] = o;
    }
}

// ---------------------------------------------------------------------------
extern "C" void kernel_launch(void* const* d_in, const int* in_sizes, int n_in,
                              void* d_out, int out_size) {
    const float *u = 0, *A = 0, *B = 0, *C = 0, *D = 0, *dt = 0;
    for (int i = 0; i < n_in; i++) {
        const float* p = (const float*)d_in[i];
        switch (in_sizes[i]) {
            case 65536: u = p;  break;
            case 4096:  A = p;  break;
            case 64:    B = p;  break;
            case 8192:  C = p;  break;
            case 128:   D = p;  break;
            case 1:     dt = p; break;
        }
    }
    const int disc_smem = (64 * 65 + 2 * 64 * MPAD) * sizeof(float);            // 51456
    const int prep_smem = (64 * 66 + 3 * 64 * 65 + 64 + 256) * sizeof(float);   // 68096
    const int gemm_smem = (128 * APAD + 128 * ZPAD + 64) * sizeof(float);       // 102656
    cudaFuncSetAttribute(k_disc, cudaFuncAttributeMaxDynamicSharedMemorySize, disc_smem);
    cudaFuncSetAttribute(k_prep, cudaFuncAttributeMaxDynamicSharedMemorySize, prep_smem);
    cudaFuncSetAttribute(k_gemm, cudaFuncAttributeMaxDynamicSharedMemorySize, gemm_smem);

    k_disc<<<1, 256, disc_smem>>>(A, B, dt);
    k_mul<<<2, 256>>>(0);
    k_mul<<<4, 256>>>(1);
    k_chain<<<49, 256>>>(C);
    k_ghat<<<136, 256>>>(C);
    k_prep<<<16, 256, prep_smem>>>(u);
    k_gemm<<<dim3(8, 128), 256, gemm_smem>>>(D, (float*)d_out);
}